// round 11
// baseline (speedup 1.0000x reference)
#include <cuda_runtime.h>
#include <cuda_bf16.h>

#define BATCH   16
#define NPTS    4096
#define DFEAT   64
#define NPOINT  1024
#define NSAMPLE 32
#define P_TOT   (BATCH*NPOINT*NSAMPLE)   // 524288
#define PBLK    (P_TOT/128)              // 4096 row-tiles of 128

typedef unsigned long long u64;

// ---------------- tf32 MMA helpers ----------------
__device__ __forceinline__ unsigned f2tf32(float x) {
    unsigned r; asm("cvt.rna.tf32.f32 %0,%1;" : "=r"(r) : "f"(x)); return r;
}
__device__ __forceinline__ void ldsm4(unsigned* r, unsigned a) {
    asm volatile("ldmatrix.sync.aligned.m8n8.x4.shared.b16 {%0,%1,%2,%3},[%4];"
        : "=r"(r[0]), "=r"(r[1]), "=r"(r[2]), "=r"(r[3]) : "r"(a));
}
__device__ __forceinline__ void mma8(float* d, const unsigned* a, unsigned b0, unsigned b1) {
    asm volatile("mma.sync.aligned.m16n8k8.row.col.f32.tf32.tf32.f32 "
        "{%0,%1,%2,%3},{%4,%5,%6,%7},{%8,%9},{%0,%1,%2,%3};"
        : "+f"(d[0]), "+f"(d[1]), "+f"(d[2]), "+f"(d[3])
        : "r"(a[0]), "r"(a[1]), "r"(a[2]), "r"(a[3]), "r"(b0), "r"(b1));
}
__device__ __forceinline__ void split4(float4 v, float* hi, float* lo) {
    float h0 = __uint_as_float(f2tf32(v.x)), h1 = __uint_as_float(f2tf32(v.y));
    float h2 = __uint_as_float(f2tf32(v.z)), h3 = __uint_as_float(f2tf32(v.w));
    *(float4*)hi = make_float4(h0, h1, h2, h3);
    *(float4*)lo = make_float4(v.x - h0, v.y - h1, v.z - h2, v.w - h3);
}

// ---------------- device scratch ----------------
__device__ float g_ptsT[(size_t)BATCH*NPTS*DFEAT];
__device__ float g_xyzT[(size_t)BATCH*NPTS*3];
__device__ float g_newxyz[(size_t)BATCH*NPOINT*3];
__device__ int   g_gidx[(size_t)BATCH*NPOINT*NSAMPLE];
__device__ float g_x1[(size_t)P_TOT*64];
__device__ float g_x2[(size_t)P_TOT*64];
__device__ float g_x3[(size_t)P_TOT*128];
__device__ float g_part[(size_t)2*128*PBLK];
__device__ float g_scale[3*128];
__device__ float g_shift[3*128];

// ---------------- prep: transpose points & xyz ----------------
__global__ void __launch_bounds__(256) prep_kernel(const float* __restrict__ xyz,
                                                   const float* __restrict__ pts) {
    int b = blockIdx.y, n0 = blockIdx.x * 64, tid = threadIdx.x;
    __shared__ float t[64][65];
    const float* src = pts + (size_t)b * DFEAT * NPTS;
#pragma unroll
    for (int j = 0; j < 16; j++) {
        int i = tid + j * 256;
        int c = i >> 6, n = i & 63;
        t[n][c] = src[(size_t)c * NPTS + n0 + n];
    }
    __syncthreads();
    float* dst = g_ptsT + ((size_t)b * NPTS + n0) * DFEAT;
#pragma unroll
    for (int j = 0; j < 16; j++) {
        int i = tid + j * 256;
        int n = i >> 6, c = i & 63;
        dst[i] = t[n][c];
    }
    if (tid < 192) {
        int c = tid / 64, n = tid % 64;
        g_xyzT[((size_t)b * NPTS + n0 + n) * 3 + c] =
            xyz[(size_t)b * 3 * NPTS + (size_t)c * NPTS + n0 + n];
    }
}

// ---------------- FPS (unchanged from R10) ----------------
__global__ void __launch_bounds__(256) fps_kernel(const float* __restrict__ xyz,
                                                  float* __restrict__ out) {
    int b = blockIdx.x, tid = threadIdx.x;
    int w = tid >> 5, lane = tid & 31;
    __shared__ float sx[NPTS], sy[NPTS], sz[NPTS];
    __shared__ u64 spk[2][8];
    const float* base = xyz + (size_t)b * 3 * NPTS;
    for (int i = tid; i < NPTS; i += 256) {
        sx[i] = base[i]; sy[i] = base[NPTS + i]; sz[i] = base[2 * NPTS + i];
    }
    float px[16], py[16], pz[16], dist[16];
#pragma unroll
    for (int j = 0; j < 16; j++) {
        int p = j * 256 + tid;
        px[j] = base[p]; py[j] = base[NPTS + p]; pz[j] = base[2 * NPTS + p];
        dist[j] = 1e10f;
    }
    __syncthreads();
    int far = 0, buf = 0;
    for (int it = 0; it < NPOINT; it++) {
        float cx = sx[far], cy = sy[far], cz = sz[far];
        if (tid == 0) {
            out[(size_t)b * 3 * NPOINT + it]              = cx;
            out[(size_t)b * 3 * NPOINT + NPOINT + it]     = cy;
            out[(size_t)b * 3 * NPOINT + 2 * NPOINT + it] = cz;
            g_newxyz[((size_t)b * NPOINT + it) * 3 + 0] = cx;
            g_newxyz[((size_t)b * NPOINT + it) * 3 + 1] = cy;
            g_newxyz[((size_t)b * NPOINT + it) * 3 + 2] = cz;
        }
        float best = -1.f; int bi = 0;
#pragma unroll
        for (int j = 0; j < 16; j++) {
            float dx = px[j] - cx, dy = py[j] - cy, dz = pz[j] - cz;
            float d = __fadd_rn(__fadd_rn(__fmul_rn(dx, dx), __fmul_rn(dy, dy)), __fmul_rn(dz, dz));
            float dm = fminf(dist[j], d);
            dist[j] = dm;
            if (dm > best) { best = dm; bi = j * 256 + tid; }
        }
        unsigned db = __float_as_uint(best);
        unsigned m  = __reduce_max_sync(0xffffffffu, db);
        unsigned cand = (db == m) ? (unsigned)bi : 0xffffffffu;
        unsigned bimin = __reduce_min_sync(0xffffffffu, cand);
        if (lane == 0)
            spk[buf][w] = ((u64)m << 32) | (u64)(0xffffffffu - bimin);
        __syncthreads();
        u64 bp = spk[buf][0];
#pragma unroll
        for (int i = 1; i < 8; i++) { u64 v = spk[buf][i]; if (v > bp) bp = v; }
        far = (int)(0xffffffffu - (unsigned)(bp & 0xffffffffu));
        buf ^= 1;
    }
}

// ---------------- ball query (unchanged numerics) ----------------
__global__ void __launch_bounds__(256) ballq_kernel(const float* __restrict__ xyz) {
    int b = blockIdx.y, tid = threadIdx.x;
    __shared__ float sx[NPTS], sy[NPTS], sz[NPTS];
    const float* base = xyz + (size_t)b * 3 * NPTS;
    for (int i = tid; i < NPTS; i += 256) {
        sx[i] = base[i]; sy[i] = base[NPTS + i]; sz[i] = base[2 * NPTS + i];
    }
    __syncthreads();
    int w = tid >> 5, lane = tid & 31;
    const float R2 = 0.01f;
    for (int ci = 0; ci < 8; ci++) {
        int s = blockIdx.x * 64 + w * 8 + ci;
        const float* cp = g_newxyz + ((size_t)b * NPOINT + s) * 3;
        float cx = cp[0], cy = cp[1], cz = cp[2];
        float s2 = __fadd_rn(__fadd_rn(__fmul_rn(cx, cx), __fmul_rn(cy, cy)), __fmul_rn(cz, cz));
        int cnt = 0, first = 0;
        int* gb = g_gidx + ((size_t)b * NPOINT + s) * NSAMPLE;
        for (int basei = 0; basei < NPTS; basei += 32) {
            int p = basei + lane;
            float x = sx[p], y = sy[p], z = sz[p];
            float p2 = __fadd_rn(__fadd_rn(__fmul_rn(x, x), __fmul_rn(y, y)), __fmul_rn(z, z));
            float dot = x * cx + y * cy + z * cz;
            float d = __fadd_rn(__fadd_rn(__fmul_rn(-2.f, dot), s2), p2);
            bool ok = !(d > R2);
            unsigned m = __ballot_sync(0xffffffffu, ok);
            if (cnt == 0 && m) first = basei + __ffs(m) - 1;
            int r = __popc(m & ((1u << lane) - 1u));
            if (ok && cnt + r < 32) gb[cnt + r] = p;
            cnt += __popc(m);
            if (cnt >= 32) break;
        }
        if (cnt < 32) {
            int j = cnt + lane;
            if (j < 32) gb[j] = first;
        }
    }
}

// ============ layer 1: gather + 3xTF32 MMA GEMM (K=72 padded) ============
// A k-layout: k0-63 = point feats, k64-66 = xyz diff, k67-71 = zero pad
__global__ void __launch_bounds__(256) l1_kernel(const float* __restrict__ W0,
                                                 const float* __restrict__ b0) {
    const int SA = 76;   // odd-quad stride -> conflict-free ldmatrix
    extern __shared__ float sm[];
    float* Ahi = sm;
    float* Alo = Ahi + 128 * SA;
    float* Whi = Alo + 128 * SA;
    float* Wlo = Whi + 64 * SA;
    __shared__ float sb[64];
    int tid = threadIdx.x, bx = blockIdx.x, p0 = bx * 128;
    for (int i = tid; i < 64 * 67; i += 256) {
        int c = i / 67, ko = i % 67;
        int kn = ko < 3 ? 64 + ko : ko - 3;
        float w = W0[i];
        float hf = __uint_as_float(f2tf32(w));
        Whi[c * SA + kn] = hf; Wlo[c * SA + kn] = w - hf;
    }
    for (int i = tid; i < 64 * 9; i += 256) {
        int c = i / 9, k = 67 + i % 9;
        Whi[c * SA + k] = 0.f; Wlo[c * SA + k] = 0.f;
    }
    if (tid < 64) sb[tid] = b0[tid];
    {
        int r = tid >> 1, h = tid & 1;
        int p = p0 + r, bb = p >> 15, s = (p >> 5) & 1023;
        int idx = g_gidx[p];
        const float* pr = g_ptsT + ((size_t)bb * NPTS + idx) * 64 + h * 32;
#pragma unroll
        for (int i = 0; i < 8; i++) {
            float4 v = *(const float4*)(pr + i * 4);
            int k = h * 32 + i * 4;
            split4(v, &Ahi[r * SA + k], &Alo[r * SA + k]);
        }
        if (h == 0) {
            const float* xr = g_xyzT + ((size_t)bb * NPTS + idx) * 3;
            const float* nr = g_newxyz + ((size_t)bb * NPOINT + s) * 3;
            float d0 = xr[0] - nr[0], d1 = xr[1] - nr[1], d2 = xr[2] - nr[2];
            float h0 = __uint_as_float(f2tf32(d0));
            float h1 = __uint_as_float(f2tf32(d1));
            float h2 = __uint_as_float(f2tf32(d2));
            Ahi[r * SA + 64] = h0; Alo[r * SA + 64] = d0 - h0;
            Ahi[r * SA + 65] = h1; Alo[r * SA + 65] = d1 - h1;
            Ahi[r * SA + 66] = h2; Alo[r * SA + 66] = d2 - h2;
        } else {
#pragma unroll
            for (int k = 67; k < 76; k++) { Ahi[r * SA + k] = 0.f; Alo[r * SA + k] = 0.f; }
        }
    }
    __syncthreads();
    int wid = tid >> 5, lane = tid & 31;
    int m0 = (wid & 3) * 32, n0 = (wid >> 2) * 32;
    int mi = lane >> 3, li = lane & 7, l4 = lane >> 2, lq = lane & 3;
    unsigned base = (unsigned)__cvta_generic_to_shared(sm);
    unsigned aoff = ((m0 + (mi & 1) * 8 + li) * SA + (mi >> 1) * 4) * 4u;
    unsigned boff = ((n0 + (mi >> 1) * 8 + li) * SA + (mi & 1) * 4) * 4u;
    unsigned aHi0 = base + aoff,               aHi1 = aHi0 + 16 * SA * 4;
    unsigned aLo0 = aHi0 + 128 * SA * 4,       aLo1 = aLo0 + 16 * SA * 4;
    unsigned wb   = base + 2 * 128 * SA * 4;
    unsigned bHi0 = wb + boff,                 bHi1 = bHi0 + 16 * SA * 4;
    unsigned bLo0 = bHi0 + 64 * SA * 4,        bLo1 = bLo0 + 16 * SA * 4;
    float acc[2][4][4];
#pragma unroll
    for (int mt = 0; mt < 2; mt++)
#pragma unroll
        for (int nt = 0; nt < 4; nt++) {
            float v0 = sb[n0 + nt * 8 + 2 * lq], v1 = sb[n0 + nt * 8 + 2 * lq + 1];
            acc[mt][nt][0] = v0; acc[mt][nt][1] = v1;
            acc[mt][nt][2] = v0; acc[mt][nt][3] = v1;
        }
    for (int ks = 0; ks < 9; ks++) {
        unsigned ko = ks * 32u;
        unsigned ah[8], al[8], bh[8], bl[8];
        ldsm4(ah, aHi0 + ko); ldsm4(ah + 4, aHi1 + ko);
        ldsm4(al, aLo0 + ko); ldsm4(al + 4, aLo1 + ko);
        ldsm4(bh, bHi0 + ko); ldsm4(bh + 4, bHi1 + ko);
        ldsm4(bl, bLo0 + ko); ldsm4(bl + 4, bLo1 + ko);
#pragma unroll
        for (int mt = 0; mt < 2; mt++)
#pragma unroll
            for (int nt = 0; nt < 4; nt++) {
                mma8(acc[mt][nt], ah + mt * 4, bh[nt * 2], bh[nt * 2 + 1]);
                mma8(acc[mt][nt], ah + mt * 4, bl[nt * 2], bl[nt * 2 + 1]);
                mma8(acc[mt][nt], al + mt * 4, bh[nt * 2], bh[nt * 2 + 1]);
            }
    }
#pragma unroll
    for (int mt = 0; mt < 2; mt++)
#pragma unroll
        for (int nt = 0; nt < 4; nt++) {
            int row = p0 + m0 + mt * 16 + l4, col = n0 + nt * 8 + 2 * lq;
            *(float2*)(g_x1 + (size_t)row * 64 + col) = make_float2(acc[mt][nt][0], acc[mt][nt][1]);
            *(float2*)(g_x1 + (size_t)(row + 8) * 64 + col) = make_float2(acc[mt][nt][2], acc[mt][nt][3]);
        }
}

// ============ layer2: affine+relu, 64->64 3xTF32 MMA ============
__global__ void __launch_bounds__(256) mlp64_kernel(const float* __restrict__ xin,
                                                    const float* __restrict__ W,
                                                    const float* __restrict__ bias,
                                                    int in_off,
                                                    float* __restrict__ xout) {
    const int SA = 68;
    extern __shared__ float sm[];
    float* Ahi = sm;
    float* Alo = Ahi + 128 * SA;
    float* Whi = Alo + 128 * SA;
    float* Wlo = Whi + 64 * SA;
    __shared__ float sb[64];
    int tid = threadIdx.x, bx = blockIdx.x, p0 = bx * 128;
    for (int i = tid; i < 64 * 64; i += 256) {
        int c = i >> 6, k = i & 63;
        float w = W[i];
        float hf = __uint_as_float(f2tf32(w));
        Whi[c * SA + k] = hf; Wlo[c * SA + k] = w - hf;
    }
    for (int i = tid; i < 64 * 4; i += 256) {
        int c = i >> 2, k = 64 + (i & 3);
        Whi[c * SA + k] = 0.f; Wlo[c * SA + k] = 0.f;
    }
    if (tid < 64) sb[tid] = bias[tid];
    {
        int r = tid >> 1, h = tid & 1;
        const float* src = xin + (size_t)(p0 + r) * 64 + h * 32;
#pragma unroll
        for (int i = 0; i < 8; i++) {
            float4 v = *(const float4*)(src + i * 4);
            int c = h * 32 + i * 4;
            v.x = fmaxf(fmaf(v.x, g_scale[in_off + c + 0], g_shift[in_off + c + 0]), 0.f);
            v.y = fmaxf(fmaf(v.y, g_scale[in_off + c + 1], g_shift[in_off + c + 1]), 0.f);
            v.z = fmaxf(fmaf(v.z, g_scale[in_off + c + 2], g_shift[in_off + c + 2]), 0.f);
            v.w = fmaxf(fmaf(v.w, g_scale[in_off + c + 3], g_shift[in_off + c + 3]), 0.f);
            split4(v, &Ahi[r * SA + c], &Alo[r * SA + c]);
        }
        if (h == 1) {
            *(float4*)&Ahi[r * SA + 64] = make_float4(0.f, 0.f, 0.f, 0.f);
            *(float4*)&Alo[r * SA + 64] = make_float4(0.f, 0.f, 0.f, 0.f);
        }
    }
    __syncthreads();
    int wid = tid >> 5, lane = tid & 31;
    int m0 = (wid & 3) * 32, n0 = (wid >> 2) * 32;
    int mi = lane >> 3, li = lane & 7, l4 = lane >> 2, lq = lane & 3;
    unsigned base = (unsigned)__cvta_generic_to_shared(sm);
    unsigned aoff = ((m0 + (mi & 1) * 8 + li) * SA + (mi >> 1) * 4) * 4u;
    unsigned boff = ((n0 + (mi >> 1) * 8 + li) * SA + (mi & 1) * 4) * 4u;
    unsigned aHi0 = base + aoff,               aHi1 = aHi0 + 16 * SA * 4;
    unsigned aLo0 = aHi0 + 128 * SA * 4,       aLo1 = aLo0 + 16 * SA * 4;
    unsigned wb   = base + 2 * 128 * SA * 4;
    unsigned bHi0 = wb + boff,                 bHi1 = bHi0 + 16 * SA * 4;
    unsigned bLo0 = bHi0 + 64 * SA * 4,        bLo1 = bLo0 + 16 * SA * 4;
    float acc[2][4][4];
#pragma unroll
    for (int mt = 0; mt < 2; mt++)
#pragma unroll
        for (int nt = 0; nt < 4; nt++) {
            float v0 = sb[n0 + nt * 8 + 2 * lq], v1 = sb[n0 + nt * 8 + 2 * lq + 1];
            acc[mt][nt][0] = v0; acc[mt][nt][1] = v1;
            acc[mt][nt][2] = v0; acc[mt][nt][3] = v1;
        }
    for (int ks = 0; ks < 8; ks++) {
        unsigned ko = ks * 32u;
        unsigned ah[8], al[8], bh[8], bl[8];
        ldsm4(ah, aHi0 + ko); ldsm4(ah + 4, aHi1 + ko);
        ldsm4(al, aLo0 + ko); ldsm4(al + 4, aLo1 + ko);
        ldsm4(bh, bHi0 + ko); ldsm4(bh + 4, bHi1 + ko);
        ldsm4(bl, bLo0 + ko); ldsm4(bl + 4, bLo1 + ko);
#pragma unroll
        for (int mt = 0; mt < 2; mt++)
#pragma unroll
            for (int nt = 0; nt < 4; nt++) {
                mma8(acc[mt][nt], ah + mt * 4, bh[nt * 2], bh[nt * 2 + 1]);
                mma8(acc[mt][nt], ah + mt * 4, bl[nt * 2], bl[nt * 2 + 1]);
                mma8(acc[mt][nt], al + mt * 4, bh[nt * 2], bh[nt * 2 + 1]);
            }
    }
#pragma unroll
    for (int mt = 0; mt < 2; mt++)
#pragma unroll
        for (int nt = 0; nt < 4; nt++) {
            int row = p0 + m0 + mt * 16 + l4, col = n0 + nt * 8 + 2 * lq;
            *(float2*)(xout + (size_t)row * 64 + col) = make_float2(acc[mt][nt][0], acc[mt][nt][1]);
            *(float2*)(xout + (size_t)(row + 8) * 64 + col) = make_float2(acc[mt][nt][2], acc[mt][nt][3]);
        }
}

// ============ layer3: affine+relu, 64->128 3xTF32 MMA ============
__global__ void __launch_bounds__(256) mlp128_kernel(const float* __restrict__ xin,
                                                     const float* __restrict__ W,
                                                     const float* __restrict__ bias,
                                                     int in_off,
                                                     float* __restrict__ xout) {
    const int SA = 68;
    extern __shared__ float sm[];
    float* Ahi = sm;
    float* Alo = Ahi + 128 * SA;
    float* Whi = Alo + 128 * SA;
    float* Wlo = Whi + 128 * SA;
    __shared__ float sb[128];
    int tid = threadIdx.x, bx = blockIdx.x, p0 = bx * 128;
    for (int i = tid; i < 128 * 64; i += 256) {
        int c = i >> 6, k = i & 63;
        float w = W[i];
        float hf = __uint_as_float(f2tf32(w));
        Whi[c * SA + k] = hf; Wlo[c * SA + k] = w - hf;
    }
    for (int i = tid; i < 128 * 4; i += 256) {
        int c = i >> 2, k = 64 + (i & 3);
        Whi[c * SA + k] = 0.f; Wlo[c * SA + k] = 0.f;
    }
    if (tid < 128) sb[tid] = bias[tid];
    {
        int r = tid >> 1, h = tid & 1;
        const float* src = xin + (size_t)(p0 + r) * 64 + h * 32;
#pragma unroll
        for (int i = 0; i < 8; i++) {
            float4 v = *(const float4*)(src + i * 4);
            int c = h * 32 + i * 4;
            v.x = fmaxf(fmaf(v.x, g_scale[in_off + c + 0], g_shift[in_off + c + 0]), 0.f);
            v.y = fmaxf(fmaf(v.y, g_scale[in_off + c + 1], g_shift[in_off + c + 1]), 0.f);
            v.z = fmaxf(fmaf(v.z, g_scale[in_off + c + 2], g_shift[in_off + c + 2]), 0.f);
            v.w = fmaxf(fmaf(v.w, g_scale[in_off + c + 3], g_shift[in_off + c + 3]), 0.f);
            split4(v, &Ahi[r * SA + c], &Alo[r * SA + c]);
        }
        if (h == 1) {
            *(float4*)&Ahi[r * SA + 64] = make_float4(0.f, 0.f, 0.f, 0.f);
            *(float4*)&Alo[r * SA + 64] = make_float4(0.f, 0.f, 0.f, 0.f);
        }
    }
    __syncthreads();
    int wid = tid >> 5, lane = tid & 31;
    int m0 = (wid & 3) * 32, n0 = (wid >> 2) * 64;     // warp covers 64 output chans
    int mi = lane >> 3, li = lane & 7, l4 = lane >> 2, lq = lane & 3;
    unsigned base = (unsigned)__cvta_generic_to_shared(sm);
    unsigned aoff = ((m0 + (mi & 1) * 8 + li) * SA + (mi >> 1) * 4) * 4u;
    unsigned boff = ((n0 + (mi >> 1) * 8 + li) * SA + (mi & 1) * 4) * 4u;
    unsigned aHi0 = base + aoff,               aHi1 = aHi0 + 16 * SA * 4;
    unsigned aLo0 = aHi0 + 128 * SA * 4,       aLo1 = aLo0 + 16 * SA * 4;
    unsigned wb   = base + 2 * 128 * SA * 4;
    unsigned bHiB = wb + boff;
    unsigned bLoB = bHiB + 128 * SA * 4;
    float acc[2][8][4];
#pragma unroll
    for (int mt = 0; mt < 2; mt++)
#pragma unroll
        for (int nt = 0; nt < 8; nt++) {
            float v0 = sb[n0 + nt * 8 + 2 * lq], v1 = sb[n0 + nt * 8 + 2 * lq + 1];
            acc[mt][nt][0] = v0; acc[mt][nt][1] = v1;
            acc[mt][nt][2] = v0; acc[mt][nt][3] = v1;
        }
    for (int ks = 0; ks < 8; ks++) {
        unsigned ko = ks * 32u;
        unsigned ah[8], al[8], bh[16], bl[16];
        ldsm4(ah, aHi0 + ko); ldsm4(ah + 4, aHi1 + ko);
        ldsm4(al, aLo0 + ko); ldsm4(al + 4, aLo1 + ko);
#pragma unroll
        for (int pr = 0; pr < 4; pr++) {
            ldsm4(bh + pr * 4, bHiB + (unsigned)(pr * 16 * SA * 4) + ko);
            ldsm4(bl + pr * 4, bLoB + (unsigned)(pr * 16 * SA * 4) + ko);
        }
#pragma unroll
        for (int mt = 0; mt < 2; mt++)
#pragma unroll
            for (int nt = 0; nt < 8; nt++) {
                mma8(acc[mt][nt], ah + mt * 4, bh[nt * 2], bh[nt * 2 + 1]);
                mma8(acc[mt][nt], ah + mt * 4, bl[nt * 2], bl[nt * 2 + 1]);
                mma8(acc[mt][nt], al + mt * 4, bh[nt * 2], bh[nt * 2 + 1]);
            }
    }
#pragma unroll
    for (int mt = 0; mt < 2; mt++)
#pragma unroll
        for (int nt = 0; nt < 8; nt++) {
            int row = p0 + m0 + mt * 16 + l4, col = n0 + nt * 8 + 2 * lq;
            *(float2*)(xout + (size_t)row * 128 + col) = make_float2(acc[mt][nt][0], acc[mt][nt][1]);
            *(float2*)(xout + (size_t)(row + 8) * 128 + col) = make_float2(acc[mt][nt][2], acc[mt][nt][3]);
        }
}

// ---------------- BN stats: deterministic column scan ----------------
__global__ void __launch_bounds__(256) stats64_kernel(const float* __restrict__ x) {
    __shared__ float sred[4][64], sredq[4][64];
    int tid = threadIdx.x, bx = blockIdx.x;
    int c = tid & 63, rl = tid >> 6;
    const float* p = x + (size_t)(bx * 1024 + rl) * 64 + c;
    float s = 0.f, q = 0.f;
    for (int r = rl; r < 1024; r += 4) { float v = *p; s += v; q += v * v; p += 4 * 64; }
    sred[rl][c] = s; sredq[rl][c] = q;
    __syncthreads();
    if (tid < 64) {
        float ss = ((sred[0][tid] + sred[1][tid]) + sred[2][tid]) + sred[3][tid];
        float qq = ((sredq[0][tid] + sredq[1][tid]) + sredq[2][tid]) + sredq[3][tid];
        g_part[(size_t)tid * 512 + bx] = ss;
        g_part[(size_t)(64 + tid) * 512 + bx] = qq;
    }
}

__global__ void __launch_bounds__(256) stats128_kernel(const float* __restrict__ x) {
    __shared__ float sred[2][128], sredq[2][128];
    int tid = threadIdx.x, bx = blockIdx.x;
    int c = tid & 127, rl = tid >> 7;
    const float* p = x + (size_t)(bx * 512 + rl) * 128 + c;
    float s = 0.f, q = 0.f;
    for (int r = rl; r < 512; r += 2) { float v = *p; s += v; q += v * v; p += 2 * 128; }
    sred[rl][c] = s; sredq[rl][c] = q;
    __syncthreads();
    if (tid < 128) {
        float ss = sred[0][tid] + sred[1][tid];
        float qq = sredq[0][tid] + sredq[1][tid];
        g_part[(size_t)tid * 1024 + bx] = ss;
        g_part[(size_t)(128 + tid) * 1024 + bx] = qq;
    }
}

// ---------------- fold BN stats into affine ----------------
__global__ void __launch_bounds__(256) fold_kernel(const float* __restrict__ gamma,
                                                   const float* __restrict__ beta,
                                                   int ch_tot, int off, int nblk) {
    int c = blockIdx.x, tid = threadIdx.x;
    __shared__ float sh1[256], sh2[256];
    float s = 0.f, q = 0.f;
    for (int i = tid; i < nblk; i += 256) {
        s += g_part[(size_t)c * nblk + i];
        q += g_part[(size_t)(ch_tot + c) * nblk + i];
    }
    sh1[tid] = s; sh2[tid] = q;
    __syncthreads();
    for (int o = 128; o; o >>= 1) {
        if (tid < o) { sh1[tid] += sh1[tid + o]; sh2[tid] += sh2[tid + o]; }
        __syncthreads();
    }
    if (tid == 0) {
        float n = (float)P_TOT;
        float mu = sh1[0] / n;
        float var = sh2[0] / n - mu * mu;
        float rs = rsqrtf(var + 1e-5f);
        float sc = gamma[c] * rs;
        g_scale[off + c] = sc;
        g_shift[off + c] = fmaf(-mu, sc, beta[c]);
    }
}

// ---------------- final BN + ReLU + maxpool over K ----------------
__global__ void __launch_bounds__(128) maxpool_kernel(float* __restrict__ out2) {
    int g0 = blockIdx.x * 16, tid = threadIdx.x;
    float sc = g_scale[256 + tid], sh = g_shift[256 + tid];
    float m[16];
#pragma unroll
    for (int gi = 0; gi < 16; gi++) {
        size_t prow = (size_t)(g0 + gi) * 32;
        float mm = 0.f;
#pragma unroll 8
        for (int k = 0; k < 32; k++) {
            float v = g_x3[(prow + k) * 128 + tid];
            mm = fmaxf(mm, fmaxf(fmaf(v, sc, sh), 0.f));
        }
        m[gi] = mm;
    }
    int b = g0 >> 10;
    int s0 = g0 & 1023;
    float* dst = out2 + ((size_t)b * 128 + tid) * NPOINT + s0;
#pragma unroll
    for (int i = 0; i < 4; i++) {
        float4 o; o.x = m[i * 4]; o.y = m[i * 4 + 1]; o.z = m[i * 4 + 2]; o.w = m[i * 4 + 3];
        *(float4*)(dst + i * 4) = o;
    }
}

// ---------------- launch ----------------
extern "C" void kernel_launch(void* const* d_in, const int* in_sizes, int n_in,
                              void* d_out, int out_size) {
    const float* xyz = (const float*)d_in[0];
    const float* pts = (const float*)d_in[1];
    const float* W0 = (const float*)d_in[2];  const float* b0 = (const float*)d_in[3];
    const float* ga0 = (const float*)d_in[4]; const float* be0 = (const float*)d_in[5];
    const float* W1 = (const float*)d_in[6];  const float* b1 = (const float*)d_in[7];
    const float* ga1 = (const float*)d_in[8]; const float* be1 = (const float*)d_in[9];
    const float* W2 = (const float*)d_in[10]; const float* b2 = (const float*)d_in[11];
    const float* ga2 = (const float*)d_in[12]; const float* be2 = (const float*)d_in[13];
    float* out = (float*)d_out;
    float* out2 = out + (size_t)BATCH * 3 * NPOINT;

    float* d_x1; cudaGetSymbolAddress((void**)&d_x1, g_x1);
    float* d_x2; cudaGetSymbolAddress((void**)&d_x2, g_x2);
    float* d_x3; cudaGetSymbolAddress((void**)&d_x3, g_x3);

    const int smem_l1   = (2 * 128 * 76 + 2 * 64 * 76) * 4;    // 116736
    const int smem_m64  = (2 * 128 * 68 + 2 * 64 * 68) * 4;    // 104448
    const int smem_m128 = (2 * 128 * 68 + 2 * 128 * 68) * 4;   // 139264
    cudaFuncSetAttribute(l1_kernel,     cudaFuncAttributeMaxDynamicSharedMemorySize, smem_l1);
    cudaFuncSetAttribute(mlp64_kernel,  cudaFuncAttributeMaxDynamicSharedMemorySize, smem_m64);
    cudaFuncSetAttribute(mlp128_kernel, cudaFuncAttributeMaxDynamicSharedMemorySize, smem_m128);

    prep_kernel<<<dim3(64, 16), 256>>>(xyz, pts);
    fps_kernel<<<16, 256>>>(xyz, out);
    ballq_kernel<<<dim3(16, 16), 256>>>(xyz);

    l1_kernel<<<PBLK, 256, smem_l1>>>(W0, b0);
    stats64_kernel<<<512, 256>>>(d_x1);
    fold_kernel<<<64, 256>>>(ga0, be0, 64, 0, 512);

    mlp64_kernel<<<PBLK, 256, smem_m64>>>(d_x1, W1, b1, 0, d_x2);
    stats64_kernel<<<512, 256>>>(d_x2);
    fold_kernel<<<64, 256>>>(ga1, be1, 64, 128, 512);

    mlp128_kernel<<<PBLK, 256, smem_m128>>>(d_x2, W2, b2, 128, d_x3);
    stats128_kernel<<<1024, 256>>>(d_x3);
    fold_kernel<<<128, 256>>>(ga2, be2, 128, 256, 1024);

    maxpool_kernel<<<BATCH * NPOINT / 16, 128>>>(out2);
}